// round 9
// baseline (speedup 1.0000x reference)
#include <cuda_runtime.h>
#include <cuda_fp16.h>
#include <cstdint>

#define B_    8
#define CIN   256
#define COUT  256
#define CINFO 256
#define LL    32768
#define CHUNK 32                 // l-positions per chunk
#define NCH   (LL / CHUNK)       // 1024 chunks per batch
#define JPITCH 40                // words per jj row (32 l + 8 pad)
#define KTSZ  (8 * JPITCH)       // 320 words per kt slab
#define BUFW  (16 * KTSZ)        // 5120 words per buffer (20 KB)

// ---------------- device scratch ----------------
__device__ float g_Ain [B_ * CIN * 2];     // [b][2i + r]
__device__ float g_Aout[B_ * 2 * COUT];    // [b][r*256 + o]

// ---------------- helpers ----------------
__device__ __forceinline__ uint32_t pack_f16x2(float lo, float hi) {
    uint32_t r;  // second source -> low half
    asm("cvt.rn.f16x2.f32 %0, %1, %2;" : "=r"(r) : "f"(hi), "f"(lo));
    return r;
}

__device__ __forceinline__ void mma16816(float* c, const uint32_t* A, uint32_t b0, uint32_t b1) {
    asm volatile(
        "mma.sync.aligned.m16n8k16.row.col.f32.f16.f16.f32 "
        "{%0,%1,%2,%3}, {%4,%5,%6,%7}, {%8,%9}, {%0,%1,%2,%3};"
        : "+f"(c[0]), "+f"(c[1]), "+f"(c[2]), "+f"(c[3])
        : "r"(A[0]), "r"(A[1]), "r"(A[2]), "r"(A[3]), "r"(b0), "r"(b1));
}

// ---------------- prologue 1: adapter vectors (1 k per warp) ----------------
__global__ void lora_adapters_kernel(const float* __restrict__ g_out,
                                     const float* __restrict__ W_ain,
                                     const float* __restrict__ W_aout) {
    __shared__ float4 sg4[CINFO / 4];
    int bx = blockIdx.x;
    int b = bx >> 7;                 // 8 batches
    int kbase = (bx & 127) * 4;      // 4 k per block
    if (threadIdx.x < CINFO / 4)
        sg4[threadIdx.x] = ((const float4*)(g_out + b * CINFO))[threadIdx.x];
    __syncthreads();
    int w = threadIdx.x >> 5, lane = threadIdx.x & 31;
    int k = kbase + w;
    const float4* wi = (const float4*)(W_ain  + (size_t)k * CINFO);
    const float4* wo = (const float4*)(W_aout + (size_t)k * CINFO);
    float ai = 0.f, ao = 0.f;
#pragma unroll
    for (int h = 0; h < 2; ++h) {
        int i = lane + 32 * h;
        float4 gv = sg4[i];
        float4 a = wi[i], o = wo[i];
        ai += a.x * gv.x + a.y * gv.y + a.z * gv.z + a.w * gv.w;
        ao += o.x * gv.x + o.y * gv.y + o.z * gv.z + o.w * gv.w;
    }
#pragma unroll
    for (int off = 16; off; off >>= 1) {
        ai += __shfl_xor_sync(0xFFFFFFFFu, ai, off);
        ao += __shfl_xor_sync(0xFFFFFFFFu, ao, off);
    }
    if (lane == 0) {
        g_Ain [b * 512 + k] = ai;
        g_Aout[b * 512 + k] = ao;
    }
}

// ---------------- main persistent GEMM (mma.sync / HMMA) ----------------
// 256 threads / 8 warps. Warp w owns cout rows [32w, 32w+32) (2 m-tiles),
// full N=32 (4 n-tiles), K=256 (16 kt) -> 128 MMAs/warp/chunk.
//
// Prologue fuses the Weff build: A fragments computed in-register from
// W_main (fp32) + adapter vectors, packed once to fp16. No g_Weff global.
//
// Per chunk: LDG.128 of chunk c+1 issued first (staged in regs), 128 MMAs
// on chunk c (hide LDG latency), pack+STS.128 of c+1, epilogue STG, 1 sync.
//
// SMEM word(kt, jj, l) = kt*320 + jj*40 + l. Consumer bank (8q+g+8nt) mod 32
// is a 32-bank permutation for both jj=q (b0) and jj=q+4 (b1). STS.128
// phases cover 32 banks. All conflict-free.
__global__ void __launch_bounds__(256, 1)
lora_main_kernel(const float* __restrict__ x, const float* __restrict__ W_main,
                 const float* __restrict__ b_main, float* __restrict__ out,
                 int per_batch) {
    extern __shared__ uint32_t sm[];   // 2 * BUFW words = 40 KB
    const int tid = threadIdx.x;
    const int lane = tid & 31;
    const int w = tid >> 5;            // 0..7
    const int cta = blockIdx.x;
    const int b  = cta / per_batch;
    const int jb = cta % per_batch;
    const int s = (jb * NCH) / per_batch;
    const int e = ((jb + 1) * NCH) / per_batch;
    if (s >= e) return;

    const float* xb = x   + (size_t)b * ((size_t)CIN * LL);
    float*       ob = out + (size_t)b * ((size_t)COUT * LL);

    const int obase = w * 32;
    const int gg = lane >> 2;    // 0..7 (MMA row group)
    const int q  = lane & 3;     // 0..3

    // ---- fused Weff: A fragments built from W_main + adapters ----
    uint32_t A0[16][4], A1[16][4];
    {
        const float* Ain = g_Ain  + b * 512;
        const float* Aou = g_Aout + b * 512;
        const int rows[4] = { obase + gg, obase + 8 + gg, obase + 16 + gg, obase + 24 + gg };
        float p0[4], p1[4];
#pragma unroll
        for (int m = 0; m < 4; ++m) {
            p0[m] = Aou[rows[m]];
            p1[m] = Aou[256 + rows[m]];
        }
#pragma unroll
        for (int kt = 0; kt < 16; ++kt) {
            float4 u = *(const float4*)(Ain + 32 * kt + 4 * q);        // cin 16kt+2q, +1
            float4 v = *(const float4*)(Ain + 32 * kt + 16 + 4 * q);   // cin 16kt+8+2q, +1
#pragma unroll
            for (int m = 0; m < 4; ++m) {
                const float* wr = W_main + (size_t)rows[m] * CIN + 16 * kt;
                float2 wlo = *(const float2*)(wr + 2 * q);
                float2 whi = *(const float2*)(wr + 8 + 2 * q);
                uint32_t flo = pack_f16x2(wlo.x + p0[m] * u.x + p1[m] * u.y,
                                          wlo.y + p0[m] * u.z + p1[m] * u.w);
                uint32_t fhi = pack_f16x2(whi.x + p0[m] * v.x + p1[m] * v.y,
                                          whi.y + p0[m] * v.z + p1[m] * v.w);
                if (m < 2) { A0[kt][m] = flo; A0[kt][2 + m] = fhi; }
                else       { A1[kt][m - 2] = flo; A1[kt][m] = fhi; }
            }
        }
    }
    const float bg00 = b_main[obase + gg];
    const float bg01 = b_main[obase + 8 + gg];
    const float bg10 = b_main[obase + 16 + gg];
    const float bg11 = b_main[obase + 24 + gg];

    // LDG staging: thread loads row-pair p = (lane>>3) + 4j, float4 at l = (lane&7)*4
    float4 sa[4], sb[4];
    const int c4 = (lane & 7) * 4;
    const int ph = lane >> 3;

    auto ldg_issue = [&](int chunk) {
        const float* base = xb + (size_t)chunk * CHUNK + c4;
#pragma unroll
        for (int j = 0; j < 4; ++j) {
            int row0 = w * 32 + 2 * (ph + 4 * j);
            sa[j] = *(const float4*)(base + (size_t)row0 * LL);
            sb[j] = *(const float4*)(base + (size_t)(row0 + 1) * LL);
        }
    };

    auto pack_sts = [&](int bufsel) {
        uint32_t* dst = sm + bufsel * BUFW;
#pragma unroll
        for (int j = 0; j < 4; ++j) {
            int p  = ph + 4 * j;
            int kt = 2 * w + (p >> 3);
            int jj = p & 7;
            uint4 v;
            v.x = pack_f16x2(sa[j].x, sb[j].x);
            v.y = pack_f16x2(sa[j].y, sb[j].y);
            v.z = pack_f16x2(sa[j].z, sb[j].z);
            v.w = pack_f16x2(sa[j].w, sb[j].w);
            *(uint4*)(dst + kt * KTSZ + jj * JPITCH + c4) = v;
        }
    };

    ldg_issue(s);
    pack_sts(0);
    __syncthreads();

    for (int c = s; c < e; ++c) {
        const int cb = (c - s) & 1;
        const bool more = (c + 1) < e;
        if (more) ldg_issue(c + 1);   // staged across the MMA block

        float acc0[4][4], acc1[4][4];
#pragma unroll
        for (int nt = 0; nt < 4; ++nt)
#pragma unroll
            for (int r = 0; r < 4; ++r) { acc0[nt][r] = 0.f; acc1[nt][r] = 0.f; }

        const uint32_t* buf = sm + cb * BUFW;
#pragma unroll
        for (int nt = 0; nt < 4; ++nt) {
            const int l = nt * 8 + gg;
            const uint32_t* p0 = buf + q * JPITCH + l;          // jj = q
            const uint32_t* p1 = buf + (q + 4) * JPITCH + l;    // jj = q+4
#pragma unroll
            for (int kt = 0; kt < 16; ++kt) {
                uint32_t b0 = p0[kt * KTSZ];
                uint32_t b1 = p1[kt * KTSZ];
                mma16816(acc0[nt], A0[kt], b0, b1);
                mma16816(acc1[nt], A1[kt], b0, b1);
            }
        }

        if (more) pack_sts(cb ^ 1);   // pack AFTER MMAs: LDG latency hidden

        // epilogue: bias + coalesced float2 stores
        {
            const size_t lc = (size_t)c * CHUNK + 2 * q;
            float* o00 = ob + (size_t)(obase + gg)      * LL + lc;
            float* o01 = ob + (size_t)(obase + gg + 8)  * LL + lc;
            float* o10 = ob + (size_t)(obase + 16 + gg) * LL + lc;
            float* o11 = ob + (size_t)(obase + 24 + gg) * LL + lc;
#pragma unroll
            for (int nt = 0; nt < 4; ++nt) {
                *(float2*)(o00 + nt * 8) = make_float2(acc0[nt][0] + bg00, acc0[nt][1] + bg00);
                *(float2*)(o01 + nt * 8) = make_float2(acc0[nt][2] + bg01, acc0[nt][3] + bg01);
                *(float2*)(o10 + nt * 8) = make_float2(acc1[nt][0] + bg10, acc1[nt][1] + bg10);
                *(float2*)(o11 + nt * 8) = make_float2(acc1[nt][2] + bg11, acc1[nt][3] + bg11);
            }
        }
        __syncthreads();
    }
}

// ---------------- launch ----------------
extern "C" void kernel_launch(void* const* d_in, const int* in_sizes, int n_in,
                              void* d_out, int out_size) {
    const float* x      = (const float*)d_in[0];
    const float* g_out  = (const float*)d_in[1];
    const float* W_main = (const float*)d_in[2];
    const float* b_main = (const float*)d_in[3];
    const float* W_ain  = (const float*)d_in[4];
    const float* W_aout = (const float*)d_in[5];
    float* out = (float*)d_out;

    int dev = 0, sms = 148;
    cudaGetDevice(&dev);
    cudaDeviceGetAttribute(&sms, cudaDevAttrMultiProcessorCount, dev);
    int per_batch = sms / B_;
    if (per_batch < 1) per_batch = 1;
    if (per_batch > NCH) per_batch = NCH;

    size_t smem = 2ull * BUFW * sizeof(uint32_t);  // 40 KB
    cudaFuncSetAttribute(lora_main_kernel, cudaFuncAttributeMaxDynamicSharedMemorySize, (int)smem);

    lora_adapters_kernel<<<B_ * 128, 128>>>(g_out, W_ain, W_aout);
    lora_main_kernel<<<per_batch * B_, 256, smem>>>(x, W_main, b_main, out, per_batch);
}